// round 14
// baseline (speedup 1.0000x reference)
#include <cuda_runtime.h>
#include <cuda_fp16.h>
#include <stdint.h>

#define SDIM 2048
#define DDIM 64
#define TQ 16
#define NTHREADS 256
#define SCH 2088            // sc row stride (u16)
#define SCW 1044            // sc row stride (u32)

// smem (70 KB -> 3 CTAs/SM)
#define OFF_SC    0                  // 16*2088*2 = 66816 (P fp16; reused as reduction buf)
#define OFF_QS    66816              // 4096
#define OFF_SSUM  70912              // 512
#define OFF_SINV  71424              // 64
#define SMEM_BYTES 71680

// fragment images
// K: u32[head][chunk][w][ks][r][l3][elem]; QK B-frag = uint2 LDG.64 (as round 13)
__device__ __align__(16) uint32_t g_k2[64u * 32u * 2048u];
// V: u32[head][chunk][kp 32][d 64] = fp16 pair (keys 2kp,2kp+1) at dim d
__device__ __align__(16) uint32_t g_v1[64u * 32u * 2048u];

__device__ __forceinline__ void mma16816h(float c[4], const uint32_t a[4], const uint32_t b[2]) {
    asm volatile(
        "mma.sync.aligned.m16n8k16.row.col.f32.f16.f16.f32 "
        "{%0,%1,%2,%3}, {%4,%5,%6,%7}, {%8,%9}, {%0,%1,%2,%3};\n"
        : "+f"(c[0]), "+f"(c[1]), "+f"(c[2]), "+f"(c[3])
        : "r"(a[0]), "r"(a[1]), "r"(a[2]), "r"(a[3]), "r"(b[0]), "r"(b[1]));
}
__device__ __forceinline__ void mma16808h(float c[4], uint32_t a0, uint32_t a1, uint32_t b0) {
    asm volatile(
        "mma.sync.aligned.m16n8k8.row.col.f32.f16.f16.f32 "
        "{%0,%1,%2,%3}, {%4,%5}, {%6}, {%0,%1,%2,%3};\n"
        : "+f"(c[0]), "+f"(c[1]), "+f"(c[2]), "+f"(c[3])
        : "r"(a0), "r"(a1), "r"(b0));
}

__device__ __forceinline__ uint32_t packh2(float x, float y) {
    __half2 h = __floats2half2_rn(x, y);
    return *(uint32_t*)&h;
}

// ---------------- pre-convert ----------------
__global__ void conv_kernel(const float* __restrict__ kg, const float* __restrict__ vg) {
    __shared__ uint16_t th[64 * 68];
    const int head = blockIdx.y, chunk = blockIdx.x, tid = threadIdx.x;
    const size_t srcoff = ((size_t)head * SDIM + (size_t)chunk * 64) * DDIM;

    {   // K -> fragment image (fp16 single), same as round 13
        uint32_t* kb = g_k2 + (size_t)(head * 32 + chunk) * 2048;
        const float4* ksrc = (const float4*)(kg + srcoff);
        #pragma unroll
        for (int rep = 0; rep < 4; ++rep) {
            int lin = tid + rep * 256;
            int k6 = lin >> 4, d4 = (lin & 15) * 4;
            float4 v = ksrc[lin];
            uint32_t h01 = packh2(v.x, v.y);
            uint32_t h23 = packh2(v.z, v.w);
            int w = k6 >> 3, r = k6 & 7;
            int j0 = d4 >> 1, j1 = j0 + 1;
            int p0 = (((w * 4 + (j0 >> 3)) * 8 + r) * 4 + (j0 & 3)) * 2 + ((j0 >> 2) & 1);
            int p1 = (((w * 4 + (j1 >> 3)) * 8 + r) * 4 + (j1 & 3)) * 2 + ((j1 >> 2) & 1);
            kb[p0] = h01;
            kb[p1] = h23;
        }
    }
    {   // V -> transpose [d][key] fp16 single, then [kp][d] pair image
        const float4* vsrc = (const float4*)(vg + srcoff);
        #pragma unroll
        for (int rep = 0; rep < 4; ++rep) {
            int lin = tid + rep * 256;
            int key = lin >> 4, d4 = (lin & 15) * 4;
            float4 v = vsrc[lin];
            th[(d4 + 0) * 68 + key] = __half_as_ushort(__float2half_rn(v.x));
            th[(d4 + 1) * 68 + key] = __half_as_ushort(__float2half_rn(v.y));
            th[(d4 + 2) * 68 + key] = __half_as_ushort(__float2half_rn(v.z));
            th[(d4 + 3) * 68 + key] = __half_as_ushort(__float2half_rn(v.w));
        }
        __syncthreads();
        uint32_t* vb = g_v1 + (size_t)(head * 32 + chunk) * 2048;
        #pragma unroll
        for (int rep = 0; rep < 8; ++rep) {
            int lin = tid + rep * 256;           // 2048: kp = lin>>6, d = lin&63
            int kp = lin >> 6, d = lin & 63;
            uint32_t hi = (uint32_t)th[d * 68 + 2 * kp] |
                          ((uint32_t)th[d * 68 + 2 * kp + 1] << 16);
            vb[lin] = hi;
        }
    }
}

// ---------------- fused attention: single pass, register-P PV ----------------
__global__ __launch_bounds__(NTHREADS, 3)
void attn_kernel(const float* __restrict__ qg, float* __restrict__ outg,
                 float* __restrict__ attng)
{
    extern __shared__ char sm[];
    uint16_t* sc   = (uint16_t*)(sm + OFF_SC);
    uint32_t* scw  = (uint32_t*)(sm + OFF_SC);
    float*    qs   = (float*)(sm + OFF_QS);
    float*    ssum = (float*)(sm + OFF_SSUM);
    float*    sinv = (float*)(sm + OFF_SINV);

    const int bh = blockIdx.y;
    const int pr = blockIdx.x;
    const int tid = threadIdx.x, lane = tid & 31, wid = tid >> 5;
    const int r4 = lane >> 2, l3 = lane & 3, c0 = l3 * 2;

    const size_t headoff = (size_t)bh * SDIM * DDIM;
    const uint2*    kimg = (const uint2*)g_k2 + (size_t)bh * 32 * 1024;
    const uint32_t* vimg = g_v1 + (size_t)bh * 32 * 2048;

    const int qbA = pr * TQ, qbB = (127 - pr) * TQ;
    const int nA = (qbA + TQ + 63) >> 6, nB = (qbB + TQ + 63) >> 6;   // nA+nB == 33

    #pragma unroll 1
    for (int t = 0; t < 2; ++t) {
        const int qbase = t ? qbB : qbA;
        const int n     = t ? nB  : nA;
        const int cendC = n * 64;

        // ---- stage q tile ----
        {
            int rl = tid >> 4, dg = (tid & 15) * 4;
            float4 v = *(const float4*)(qg + headoff + (size_t)(qbase + rl) * DDIM + dg);
            *(float4*)(qs + rl * DDIM + dg) =
                make_float4(v.x * 0.125f, v.y * 0.125f, v.z * 0.125f, v.w * 0.125f);
        }
        __syncthreads();

        // Q A-fragments (fp16 single)
        uint32_t aq[4][4];
        #pragma unroll
        for (int ks = 0; ks < 4; ++ks) {
            const float* q0 = qs + r4 * DDIM + ks * 16;
            const float* q1 = q0 + 8 * DDIM;
            aq[ks][0] = packh2(q0[c0],     q0[c0 + 1]);
            aq[ks][1] = packh2(q1[c0],     q1[c0 + 1]);
            aq[ks][2] = packh2(q0[c0 + 8], q0[c0 + 9]);
            aq[ks][3] = packh2(q1[c0 + 8], q1[c0 + 9]);
        }

        // ---------------- single pass: QK + exp + sums + sc + PV ----------------
        float s0 = 0.f, s1 = 0.f;
        float oc[8][4];
        #pragma unroll
        for (int nt = 0; nt < 8; ++nt)
            oc[nt][0] = oc[nt][1] = oc[nt][2] = oc[nt][3] = 0.f;

        const int row0 = qbase + r4, row1 = row0 + 8;
        const int kidx = (wid << 7) + (r4 << 2) + l3;
        const int vbase = (4 * wid + l3) * 64 + r4;

        uint2 kf[4];
        #pragma unroll
        for (int ks = 0; ks < 4; ++ks) kf[ks] = kimg[kidx + (ks << 5)];

        #pragma unroll 1
        for (int c = 0; c < n; ++c) {
            // V fragments for this chunk (consumed at loop end -> latency covered)
            const uint32_t* vc = vimg + (size_t)c * 2048;
            uint32_t vf[8];
            #pragma unroll
            for (int nt = 0; nt < 8; ++nt) vf[nt] = vc[vbase + nt * 8];

            // next-chunk K prefetch
            uint2 kn[4];
            if (c + 1 < n) {
                const uint2* kc = kimg + (size_t)(c + 1) * 1024;
                #pragma unroll
                for (int ks = 0; ks < 4; ++ks) kn[ks] = kc[kidx + (ks << 5)];
            }

            // QK: 4 k16 MMAs, 2 accumulators
            float a0[4] = {0,0,0,0}, a1[4] = {0,0,0,0};
            { uint32_t b[2] = {kf[0].x, kf[0].y}; mma16816h(a0, aq[0], b); }
            { uint32_t b[2] = {kf[1].x, kf[1].y}; mma16816h(a1, aq[1], b); }
            { uint32_t b[2] = {kf[2].x, kf[2].y}; mma16816h(a0, aq[2], b); }
            { uint32_t b[2] = {kf[3].x, kf[3].y}; mma16816h(a1, aq[3], b); }

            const int col = c * 64 + wid * 8 + c0;
            float p0 = (col     <= row0) ? __expf(a0[0] + a1[0]) : 0.f;
            float p1 = (col + 1 <= row0) ? __expf(a0[1] + a1[1]) : 0.f;
            float p2 = (col     <= row1) ? __expf(a0[2] + a1[2]) : 0.f;
            float p3 = (col + 1 <= row1) ? __expf(a0[3] + a1[3]) : 0.f;
            s0 += p0 + p1;
            s1 += p2 + p3;

            const uint32_t h01 = packh2(p0, p1);
            const uint32_t h23 = packh2(p2, p3);
            scw[r4 * SCW       + (col >> 1)] = h01;
            scw[(r4 + 8) * SCW + (col >> 1)] = h23;

            // PV: warp's own 8-key slice, k8 MMAs, P straight from registers
            #pragma unroll
            for (int nt = 0; nt < 8; ++nt)
                mma16808h(oc[nt], h01, h23, vf[nt]);

            #pragma unroll
            for (int ks = 0; ks < 4; ++ks) kf[ks] = kn[ks];
        }

        // ---------------- row sums -> sinv ----------------
        s0 += __shfl_xor_sync(0xffffffffu, s0, 1);
        s0 += __shfl_xor_sync(0xffffffffu, s0, 2);
        s1 += __shfl_xor_sync(0xffffffffu, s1, 1);
        s1 += __shfl_xor_sync(0xffffffffu, s1, 2);
        if (l3 == 0) {
            ssum[r4 * 8 + wid]       = s0;
            ssum[(r4 + 8) * 8 + wid] = s1;
        }
        __syncthreads();
        if (tid < TQ) {
            float s = 0.f;
            #pragma unroll
            for (int w = 0; w < 8; ++w) s += ssum[tid * 8 + w];
            sinv[tid] = 1.0f / s;
        }
        __syncthreads();

        // ---------------- attn write sweep (coalesced) ----------------
        if (attng) {
            #pragma unroll 1
            for (int r = 0; r < TQ; ++r) {
                const float invr = sinv[r];
                float* arow = attng + ((size_t)bh * SDIM + qbase + r) * SDIM;
                #pragma unroll
                for (int half = 0; half < 2; ++half) {
                    const int j = tid * 4 + half * 1024;
                    float4 o;
                    if (j < cendC) {
                        uint2 pk = *(const uint2*)(sc + r * SCH + j);
                        float2 fa = __half22float2(*(__half2*)&pk.x);
                        float2 fb = __half22float2(*(__half2*)&pk.y);
                        o = make_float4(fa.x * invr, fa.y * invr, fb.x * invr, fb.y * invr);
                    } else {
                        o = make_float4(0.f, 0.f, 0.f, 0.f);
                    }
                    __stcs((float4*)(arow + j), o);
                }
            }
        }
        __syncthreads();   // sc reads done before reduction overwrites it

        // ---------------- PV cross-warp reduction (reuse sc smem) ----------------
        {
            float* red = (float*)(sm + OFF_SC);     // [8 warps][16 rows][64 d]
            float* wb = red + wid * 1024;
            #pragma unroll
            for (int nt = 0; nt < 8; ++nt) {
                const int d = nt * 8 + c0;
                *(float2*)(wb + r4 * 64 + d)       = make_float2(oc[nt][0], oc[nt][1]);
                *(float2*)(wb + (r4 + 8) * 64 + d) = make_float2(oc[nt][2], oc[nt][3]);
            }
            __syncthreads();
            const int row = tid >> 4, d = (tid & 15) * 4;
            float4 a = make_float4(0.f, 0.f, 0.f, 0.f);
            #pragma unroll
            for (int w = 0; w < 8; ++w) {
                float4 tv = *(const float4*)(red + w * 1024 + row * 64 + d);
                a.x += tv.x; a.y += tv.y; a.z += tv.z; a.w += tv.w;
            }
            const float sv = sinv[row];
            *(float4*)(outg + headoff + (size_t)(qbase + row) * DDIM + d) =
                make_float4(a.x * sv, a.y * sv, a.z * sv, a.w * sv);
        }
        __syncthreads();   // red/sc reuse guard before next tile
    }
}

extern "C" void kernel_launch(void* const* d_in, const int* in_sizes, int n_in,
                              void* d_out, int out_size) {
    const float* q = (const float*)d_in[0];
    const float* k = (const float*)d_in[1];
    const float* v = (const float*)d_in[2];

    float* out = (float*)d_out;
    const long long OUT_E  = 64LL * 2048 * 64;
    const long long ATTN_E = 64LL * 2048 * 2048;
    float* attn = ((long long)out_size >= OUT_E + ATTN_E) ? out + OUT_E : nullptr;

    {
        dim3 g(32, 64);
        conv_kernel<<<g, 256>>>(k, v);
    }

    cudaFuncSetAttribute(attn_kernel,
                         cudaFuncAttributeMaxDynamicSharedMemorySize, SMEM_BYTES);
    dim3 grid(64, 64);   // 64 balanced tile-pairs x 64 heads
    attn_kernel<<<grid, NTHREADS, SMEM_BYTES>>>(q, out, attn);
}

// round 15
// speedup vs baseline: 1.3358x; 1.3358x over previous
#include <cuda_runtime.h>
#include <cuda_fp16.h>
#include <stdint.h>

#define SDIM 2048
#define DDIM 64
#define TQ 16
#define NTHREADS 256
#define SCH 2088            // sc row stride (u16)
#define SCW 1044            // sc row stride (u32)

// smem byte offsets (70 KB total -> 3 CTAs/SM)
#define OFF_SC    0                  // 16*2088*2 = 66816
#define OFF_QS    66816              // 4096
#define OFF_SSUM  70912              // 512
#define OFF_SINV  71424              // 64
#define SMEM_BYTES 71680

// fragment images
// K: u32[head][chunk][w][ks][r][l3][elem]; QK B-frag = uint2 LDG.64
__device__ __align__(16) uint32_t g_k2[64u * 32u * 2048u];
// V: uint4[head][chunk][kgrp2 2][d 64][l3 4] = {kgA kp0, kgA kp1, kgB kp0, kgB kp1}
__device__ __align__(16) uint4    g_v4[64u * 32u * 512u];

__device__ __forceinline__ void mma16816h(float c[4], const uint32_t a[4], const uint32_t b[2]) {
    asm volatile(
        "mma.sync.aligned.m16n8k16.row.col.f32.f16.f16.f32 "
        "{%0,%1,%2,%3}, {%4,%5,%6,%7}, {%8,%9}, {%0,%1,%2,%3};\n"
        : "+f"(c[0]), "+f"(c[1]), "+f"(c[2]), "+f"(c[3])
        : "r"(a[0]), "r"(a[1]), "r"(a[2]), "r"(a[3]), "r"(b[0]), "r"(b[1]));
}

__device__ __forceinline__ uint32_t packh2(float x, float y) {
    __half2 h = __floats2half2_rn(x, y);
    return *(uint32_t*)&h;
}

// ---------------- pre-convert: K and V^T into fragment images ----------------
__global__ void conv_kernel(const float* __restrict__ kg, const float* __restrict__ vg) {
    __shared__ uint16_t th[64 * 68];
    const int head = blockIdx.y, chunk = blockIdx.x, tid = threadIdx.x;
    const size_t srcoff = ((size_t)head * SDIM + (size_t)chunk * 64) * DDIM;

    {   // K -> fragment image (fp16 single)
        uint32_t* kb = g_k2 + (size_t)(head * 32 + chunk) * 2048;
        const float4* ksrc = (const float4*)(kg + srcoff);
        #pragma unroll
        for (int rep = 0; rep < 4; ++rep) {
            int lin = tid + rep * 256;
            int k6 = lin >> 4, d4 = (lin & 15) * 4;
            float4 v = ksrc[lin];
            uint32_t h01 = packh2(v.x, v.y);
            uint32_t h23 = packh2(v.z, v.w);
            int w = k6 >> 3, r = k6 & 7;
            int j0 = d4 >> 1, j1 = j0 + 1;
            int p0 = (((w * 4 + (j0 >> 3)) * 8 + r) * 4 + (j0 & 3)) * 2 + ((j0 >> 2) & 1);
            int p1 = (((w * 4 + (j1 >> 3)) * 8 + r) * 4 + (j1 & 3)) * 2 + ((j1 >> 2) & 1);
            kb[p0] = h01;
            kb[p1] = h23;
        }
    }
    {   // V -> transpose [d][key] fp16 single, then paired-fragment uint4 image
        const float4* vsrc = (const float4*)(vg + srcoff);
        #pragma unroll
        for (int rep = 0; rep < 4; ++rep) {
            int lin = tid + rep * 256;
            int key = lin >> 4, d4 = (lin & 15) * 4;
            float4 v = vsrc[lin];
            th[(d4 + 0) * 68 + key] = __half_as_ushort(__float2half_rn(v.x));
            th[(d4 + 1) * 68 + key] = __half_as_ushort(__float2half_rn(v.y));
            th[(d4 + 2) * 68 + key] = __half_as_ushort(__float2half_rn(v.z));
            th[(d4 + 3) * 68 + key] = __half_as_ushort(__float2half_rn(v.w));
        }
        __syncthreads();
        uint4* vb = g_v4 + (size_t)(head * 32 + chunk) * 512;
        #pragma unroll
        for (int rep = 0; rep < 2; ++rep) {
            int lin = tid + rep * 256;           // 512 uint4
            int l3 = lin & 3, d = (lin >> 2) & 63, kgrp2 = lin >> 8;
            int kgA = kgrp2 * 2, kgB = kgA + 1;
            #define VPAIR(KG, W) ({ \
                int kp = (KG) * 8 + l3 + (W) * 4; \
                (uint32_t)th[d * 68 + 2 * kp] | ((uint32_t)th[d * 68 + 2 * kp + 1] << 16); })
            uint32_t a0 = VPAIR(kgA, 0), a1 = VPAIR(kgA, 1);
            uint32_t b0 = VPAIR(kgB, 0), b1 = VPAIR(kgB, 1);
            #undef VPAIR
            vb[lin] = make_uint4(a0, a1, b0, b1);
        }
    }
}

// ---------------- fused attention: two-pass, LDG fragments, 3 CTAs/SM ----------------
__global__ __launch_bounds__(NTHREADS, 3)
void attn_kernel(const float* __restrict__ qg, float* __restrict__ outg,
                 float* __restrict__ attng)
{
    extern __shared__ char sm[];
    uint16_t* sc   = (uint16_t*)(sm + OFF_SC);
    uint32_t* scw  = (uint32_t*)(sm + OFF_SC);
    float*    qs   = (float*)(sm + OFF_QS);
    float*    ssum = (float*)(sm + OFF_SSUM);
    float*    sinv = (float*)(sm + OFF_SINV);

    const int bh = blockIdx.y;
    const int pr = blockIdx.x;                  // pair id, 0..63
    const int tid = threadIdx.x, lane = tid & 31, wid = tid >> 5;
    const int r4 = lane >> 2, l3 = lane & 3, c0 = l3 * 2;

    const size_t headoff = (size_t)bh * SDIM * DDIM;
    const uint2* kimg = (const uint2*)g_k2 + (size_t)bh * 32 * 1024;
    const uint4* vimg = g_v4 + (size_t)bh * 32 * 512;

    const int qbA = pr * TQ, qbB = (127 - pr) * TQ;
    const int nA = (qbA + TQ + 63) >> 6, nB = (qbB + TQ + 63) >> 6;   // nA+nB == 33

    #pragma unroll 1
    for (int t = 0; t < 2; ++t) {
        const int qbase = t ? qbB : qbA;
        const int n     = t ? nB  : nA;
        const int cendC = n * 64;

        // ---- stage q tile ----
        {
            int rl = tid >> 4, dg = (tid & 15) * 4;
            float4 v = *(const float4*)(qg + headoff + (size_t)(qbase + rl) * DDIM + dg);
            *(float4*)(qs + rl * DDIM + dg) =
                make_float4(v.x * 0.125f, v.y * 0.125f, v.z * 0.125f, v.w * 0.125f);
        }
        __syncthreads();

        // Q A-fragments (fp16 single)
        uint32_t aq[4][4];
        #pragma unroll
        for (int ks = 0; ks < 4; ++ks) {
            const float* q0 = qs + r4 * DDIM + ks * 16;
            const float* q1 = q0 + 8 * DDIM;
            aq[ks][0] = packh2(q0[c0],     q0[c0 + 1]);
            aq[ks][1] = packh2(q1[c0],     q1[c0 + 1]);
            aq[ks][2] = packh2(q0[c0 + 8], q0[c0 + 9]);
            aq[ks][3] = packh2(q1[c0 + 8], q1[c0 + 9]);
        }

        // ---------------- pass 1: QK (fp16, 4 MMAs) + exp + sums + sc ----------------
        float s0 = 0.f, s1 = 0.f;
        const int row0 = qbase + r4, row1 = row0 + 8;
        const int kidx = (wid << 7) + (r4 << 2) + l3;

        uint2 kf[4];
        #pragma unroll
        for (int ks = 0; ks < 4; ++ks) kf[ks] = kimg[kidx + (ks << 5)];

        #pragma unroll 1
        for (int c = 0; c < n; ++c) {
            uint2 kn[4];
            if (c + 1 < n) {
                const uint2* kc = kimg + (size_t)(c + 1) * 1024;
                #pragma unroll
                for (int ks = 0; ks < 4; ++ks) kn[ks] = kc[kidx + (ks << 5)];
            }

            float a0[4] = {0,0,0,0}, a1[4] = {0,0,0,0};
            { uint32_t b[2] = {kf[0].x, kf[0].y}; mma16816h(a0, aq[0], b); }
            { uint32_t b[2] = {kf[1].x, kf[1].y}; mma16816h(a1, aq[1], b); }
            { uint32_t b[2] = {kf[2].x, kf[2].y}; mma16816h(a0, aq[2], b); }
            { uint32_t b[2] = {kf[3].x, kf[3].y}; mma16816h(a1, aq[3], b); }

            const float acc0 = a0[0] + a1[0];
            const float acc1 = a0[1] + a1[1];
            const float acc2 = a0[2] + a1[2];
            const float acc3 = a0[3] + a1[3];

            const int col = c * 64 + wid * 8 + c0;
            float p0 = (col     <= row0) ? __expf(acc0) : 0.f;
            float p1 = (col + 1 <= row0) ? __expf(acc1) : 0.f;
            float p2 = (col     <= row1) ? __expf(acc2) : 0.f;
            float p3 = (col + 1 <= row1) ? __expf(acc3) : 0.f;
            s0 += p0 + p1;
            s1 += p2 + p3;

            scw[r4 * SCW       + (col >> 1)] = packh2(p0, p1);
            scw[(r4 + 8) * SCW + (col >> 1)] = packh2(p2, p3);

            #pragma unroll
            for (int ks = 0; ks < 4; ++ks) kf[ks] = kn[ks];
        }

        // ---------------- row sums -> sinv ----------------
        s0 += __shfl_xor_sync(0xffffffffu, s0, 1);
        s0 += __shfl_xor_sync(0xffffffffu, s0, 2);
        s1 += __shfl_xor_sync(0xffffffffu, s1, 1);
        s1 += __shfl_xor_sync(0xffffffffu, s1, 2);
        if (l3 == 0) {
            ssum[r4 * 8 + wid]       = s0;
            ssum[(r4 + 8) * 8 + wid] = s1;
        }
        __syncthreads();
        if (tid < TQ) {
            float s = 0.f;
            #pragma unroll
            for (int w = 0; w < 8; ++w) s += ssum[tid * 8 + w];
            sinv[tid] = 1.0f / s;
        }
        __syncthreads();

        // ---------------- pass 2: PV (fp16 k16, 4 MMAs) + attn write ----------------
        float oca[4] = {0.f, 0.f, 0.f, 0.f};
        float ocb[4] = {0.f, 0.f, 0.f, 0.f};
        const int dloc = wid * 8 + r4;
        const int vidx = dloc * 4 + l3;             // kgrp2=0 slot; +256 for kgrp2=1
        const int arown = tid >> 4;
        const float invr = sinv[arown];
        float* arow = attng ? attng + ((size_t)bh * SDIM + qbase + arown) * SDIM : (float*)0;

        #pragma unroll 1
        for (int c = 0; c < n; ++c) {
            const uint4* vc = vimg + (size_t)c * 512;
            uint4 vv0 = vc[vidx];          // kg0, kg1
            uint4 vv1 = vc[vidx + 256];    // kg2, kg3

            const int cb2 = c * 32;
            #define PVS(OC, BX, BY, KG) { \
                uint32_t a[4]; \
                a[0] = scw[r4 * SCW       + cb2 + (KG) * 8 + l3]; \
                a[1] = scw[(r4 + 8) * SCW + cb2 + (KG) * 8 + l3]; \
                a[2] = scw[r4 * SCW       + cb2 + (KG) * 8 + 4 + l3]; \
                a[3] = scw[(r4 + 8) * SCW + cb2 + (KG) * 8 + 4 + l3]; \
                uint32_t b2[2] = {BX, BY}; \
                mma16816h(OC, a, b2); }
            PVS(oca, vv0.x, vv0.y, 0)
            PVS(ocb, vv0.z, vv0.w, 1)
            PVS(oca, vv1.x, vv1.y, 2)
            PVS(ocb, vv1.z, vv1.w, 3)
            #undef PVS

            if (arow) {
                const int jc = c * 64 + (tid & 15) * 4;
                uint2 pk = *(const uint2*)(sc + arown * SCH + jc);
                float2 fa = __half22float2(*(__half2*)&pk.x);
                float2 fb = __half22float2(*(__half2*)&pk.y);
                __stcs((float4*)(arow + jc),
                       make_float4(fa.x * invr, fa.y * invr, fb.x * invr, fb.y * invr));
            }
        }

        // attn tail zeros
        if (arow) {
            for (int j = cendC + (tid & 15) * 4; j < SDIM; j += 64)
                __stcs((float4*)(arow + j), make_float4(0.f, 0.f, 0.f, 0.f));
        }

        // output write (warp-owned 16x8 block)
        {
            const float sv0 = sinv[r4], sv1 = sinv[r4 + 8];
            float* orow = outg + headoff + (size_t)(qbase + r4) * DDIM;
            const int dc = wid * 8 + c0;
            *(float2*)(orow + dc) =
                make_float2((oca[0] + ocb[0]) * sv0, (oca[1] + ocb[1]) * sv0);
            *(float2*)(orow + 8 * DDIM + dc) =
                make_float2((oca[2] + ocb[2]) * sv1, (oca[3] + ocb[3]) * sv1);
        }
        __syncthreads();   // sc/qs reuse guard before next tile
    }
}

extern "C" void kernel_launch(void* const* d_in, const int* in_sizes, int n_in,
                              void* d_out, int out_size) {
    const float* q = (const float*)d_in[0];
    const float* k = (const float*)d_in[1];
    const float* v = (const float*)d_in[2];

    float* out = (float*)d_out;
    const long long OUT_E  = 64LL * 2048 * 64;
    const long long ATTN_E = 64LL * 2048 * 2048;
    float* attn = ((long long)out_size >= OUT_E + ATTN_E) ? out + OUT_E : nullptr;

    {
        dim3 g(32, 64);
        conv_kernel<<<g, 256>>>(k, v);
    }

    cudaFuncSetAttribute(attn_kernel,
                         cudaFuncAttributeMaxDynamicSharedMemorySize, SMEM_BYTES);
    dim3 grid(64, 64);   // 64 balanced tile-pairs x 64 heads
    attn_kernel<<<grid, NTHREADS, SMEM_BYTES>>>(q, out, attn);
}

// round 16
// speedup vs baseline: 1.3453x; 1.0071x over previous
#include <cuda_runtime.h>
#include <cuda_fp16.h>
#include <stdint.h>

#define SDIM 2048
#define DDIM 64
#define TQ 16
#define NTHREADS 256
#define SCH 2088            // sc row stride (u16)
#define SCW 1044            // sc row stride (u32)

// smem byte offsets (70 KB total -> 3 CTAs/SM)
#define OFF_SC    0                  // 16*2088*2 = 66816
#define OFF_QS    66816              // 4096
#define OFF_SSUM  70912              // 512
#define OFF_SINV  71424              // 64
#define SMEM_BYTES 71680

// fragment images
// K: u32[head][chunk][w][ks][r][l3][elem]; QK B-frag = uint2 LDG.64
__device__ __align__(16) uint32_t g_k2[64u * 32u * 2048u];
// V: uint4[head][chunk][kgrp2 2][d 64][l3 4] = {kgA kp0, kgA kp1, kgB kp0, kgB kp1}
__device__ __align__(16) uint4    g_v4[64u * 32u * 512u];

__device__ __forceinline__ void mma16816h(float c[4], const uint32_t a[4], const uint32_t b[2]) {
    asm volatile(
        "mma.sync.aligned.m16n8k16.row.col.f32.f16.f16.f32 "
        "{%0,%1,%2,%3}, {%4,%5,%6,%7}, {%8,%9}, {%0,%1,%2,%3};\n"
        : "+f"(c[0]), "+f"(c[1]), "+f"(c[2]), "+f"(c[3])
        : "r"(a[0]), "r"(a[1]), "r"(a[2]), "r"(a[3]), "r"(b[0]), "r"(b[1]));
}

__device__ __forceinline__ uint32_t packh2(float x, float y) {
    __half2 h = __floats2half2_rn(x, y);
    return *(uint32_t*)&h;
}

// ---------------- pre-convert: K and V^T into fragment images ----------------
__global__ void conv_kernel(const float* __restrict__ kg, const float* __restrict__ vg) {
    __shared__ uint16_t th[64 * 68];
    const int head = blockIdx.y, chunk = blockIdx.x, tid = threadIdx.x;
    const size_t srcoff = ((size_t)head * SDIM + (size_t)chunk * 64) * DDIM;

    {   // K -> fragment image (fp16 single)
        uint32_t* kb = g_k2 + (size_t)(head * 32 + chunk) * 2048;
        const float4* ksrc = (const float4*)(kg + srcoff);
        #pragma unroll
        for (int rep = 0; rep < 4; ++rep) {
            int lin = tid + rep * 256;
            int k6 = lin >> 4, d4 = (lin & 15) * 4;
            float4 v = ksrc[lin];
            uint32_t h01 = packh2(v.x, v.y);
            uint32_t h23 = packh2(v.z, v.w);
            int w = k6 >> 3, r = k6 & 7;
            int j0 = d4 >> 1, j1 = j0 + 1;
            int p0 = (((w * 4 + (j0 >> 3)) * 8 + r) * 4 + (j0 & 3)) * 2 + ((j0 >> 2) & 1);
            int p1 = (((w * 4 + (j1 >> 3)) * 8 + r) * 4 + (j1 & 3)) * 2 + ((j1 >> 2) & 1);
            kb[p0] = h01;
            kb[p1] = h23;
        }
    }
    {   // V -> transpose [d][key] fp16 single, then paired-fragment uint4 image
        const float4* vsrc = (const float4*)(vg + srcoff);
        #pragma unroll
        for (int rep = 0; rep < 4; ++rep) {
            int lin = tid + rep * 256;
            int key = lin >> 4, d4 = (lin & 15) * 4;
            float4 v = vsrc[lin];
            th[(d4 + 0) * 68 + key] = __half_as_ushort(__float2half_rn(v.x));
            th[(d4 + 1) * 68 + key] = __half_as_ushort(__float2half_rn(v.y));
            th[(d4 + 2) * 68 + key] = __half_as_ushort(__float2half_rn(v.z));
            th[(d4 + 3) * 68 + key] = __half_as_ushort(__float2half_rn(v.w));
        }
        __syncthreads();
        uint4* vb = g_v4 + (size_t)(head * 32 + chunk) * 512;
        #pragma unroll
        for (int rep = 0; rep < 2; ++rep) {
            int lin = tid + rep * 256;           // 512 uint4
            int l3 = lin & 3, d = (lin >> 2) & 63, kgrp2 = lin >> 8;
            int kgA = kgrp2 * 2, kgB = kgA + 1;
            #define VPAIR(KG, W) ({ \
                int kp = (KG) * 8 + l3 + (W) * 4; \
                (uint32_t)th[d * 68 + 2 * kp] | ((uint32_t)th[d * 68 + 2 * kp + 1] << 16); })
            uint32_t a0 = VPAIR(kgA, 0), a1 = VPAIR(kgA, 1);
            uint32_t b0 = VPAIR(kgB, 0), b1 = VPAIR(kgB, 1);
            #undef VPAIR
            vb[lin] = make_uint4(a0, a1, b0, b1);
        }
    }
}

// ---------------- fused attention: two-pass, LDG fragments, 3 CTAs/SM ----------------
__global__ __launch_bounds__(NTHREADS, 3)
void attn_kernel(const float* __restrict__ qg, float* __restrict__ outg,
                 float* __restrict__ attng)
{
    extern __shared__ char sm[];
    uint16_t* sc   = (uint16_t*)(sm + OFF_SC);
    uint32_t* scw  = (uint32_t*)(sm + OFF_SC);
    float*    qs   = (float*)(sm + OFF_QS);
    float*    ssum = (float*)(sm + OFF_SSUM);
    float*    sinv = (float*)(sm + OFF_SINV);

    const int bh = blockIdx.y;
    const int pr = blockIdx.x;                  // pair id, 0..63
    const int tid = threadIdx.x, lane = tid & 31, wid = tid >> 5;
    const int r4 = lane >> 2, l3 = lane & 3, c0 = l3 * 2;

    const size_t headoff = (size_t)bh * SDIM * DDIM;
    const uint2* kimg = (const uint2*)g_k2 + (size_t)bh * 32 * 1024;
    const uint4* vimg = g_v4 + (size_t)bh * 32 * 512;

    const int qbA = pr * TQ, qbB = (127 - pr) * TQ;
    const int nA = (qbA + TQ + 63) >> 6, nB = (qbB + TQ + 63) >> 6;   // nA+nB == 33

    #pragma unroll 1
    for (int t = 0; t < 2; ++t) {
        const int qbase = t ? qbB : qbA;
        const int n     = t ? nB  : nA;
        const int cendC = n * 64;

        // ---- stage q tile ----
        {
            int rl = tid >> 4, dg = (tid & 15) * 4;
            float4 v = *(const float4*)(qg + headoff + (size_t)(qbase + rl) * DDIM + dg);
            *(float4*)(qs + rl * DDIM + dg) =
                make_float4(v.x * 0.125f, v.y * 0.125f, v.z * 0.125f, v.w * 0.125f);
        }
        __syncthreads();

        // Q A-fragments (fp16 single)
        uint32_t aq[4][4];
        #pragma unroll
        for (int ks = 0; ks < 4; ++ks) {
            const float* q0 = qs + r4 * DDIM + ks * 16;
            const float* q1 = q0 + 8 * DDIM;
            aq[ks][0] = packh2(q0[c0],     q0[c0 + 1]);
            aq[ks][1] = packh2(q1[c0],     q1[c0 + 1]);
            aq[ks][2] = packh2(q0[c0 + 8], q0[c0 + 9]);
            aq[ks][3] = packh2(q1[c0 + 8], q1[c0 + 9]);
        }

        // ---------------- pass 1: QK (fp16, 4 MMAs) + exp + sums + sc ----------------
        float s0 = 0.f, s1 = 0.f;
        const int row0 = qbase + r4, row1 = row0 + 8;
        const int kidx = (wid << 7) + (r4 << 2) + l3;

        uint2 kf[4];
        #pragma unroll
        for (int ks = 0; ks < 4; ++ks) kf[ks] = kimg[kidx + (ks << 5)];

        #pragma unroll 1
        for (int c = 0; c < n; ++c) {
            uint2 kn[4];
            if (c + 1 < n) {
                const uint2* kc = kimg + (size_t)(c + 1) * 1024;
                #pragma unroll
                for (int ks = 0; ks < 4; ++ks) kn[ks] = kc[kidx + (ks << 5)];
            }

            float a0[4] = {0,0,0,0}, a1[4] = {0,0,0,0};
            { uint32_t b[2] = {kf[0].x, kf[0].y}; mma16816h(a0, aq[0], b); }
            { uint32_t b[2] = {kf[1].x, kf[1].y}; mma16816h(a1, aq[1], b); }
            { uint32_t b[2] = {kf[2].x, kf[2].y}; mma16816h(a0, aq[2], b); }
            { uint32_t b[2] = {kf[3].x, kf[3].y}; mma16816h(a1, aq[3], b); }

            const float acc0 = a0[0] + a1[0];
            const float acc1 = a0[1] + a1[1];
            const float acc2 = a0[2] + a1[2];
            const float acc3 = a0[3] + a1[3];

            const int col = c * 64 + wid * 8 + c0;
            float p0 = (col     <= row0) ? __expf(acc0) : 0.f;
            float p1 = (col + 1 <= row0) ? __expf(acc1) : 0.f;
            float p2 = (col     <= row1) ? __expf(acc2) : 0.f;
            float p3 = (col + 1 <= row1) ? __expf(acc3) : 0.f;
            s0 += p0 + p1;
            s1 += p2 + p3;

            scw[r4 * SCW       + (col >> 1)] = packh2(p0, p1);
            scw[(r4 + 8) * SCW + (col >> 1)] = packh2(p2, p3);

            #pragma unroll
            for (int ks = 0; ks < 4; ++ks) kf[ks] = kn[ks];
        }

        // ---------------- row sums -> sinv ----------------
        s0 += __shfl_xor_sync(0xffffffffu, s0, 1);
        s0 += __shfl_xor_sync(0xffffffffu, s0, 2);
        s1 += __shfl_xor_sync(0xffffffffu, s1, 1);
        s1 += __shfl_xor_sync(0xffffffffu, s1, 2);
        if (l3 == 0) {
            ssum[r4 * 8 + wid]       = s0;
            ssum[(r4 + 8) * 8 + wid] = s1;
        }
        __syncthreads();
        if (tid < TQ) {
            float s = 0.f;
            #pragma unroll
            for (int w = 0; w < 8; ++w) s += ssum[tid * 8 + w];
            sinv[tid] = 1.0f / s;
        }
        __syncthreads();

        // ---------------- pass 2: PV (fp16 k16, 4 MMAs) + attn write ----------------
        float oca[4] = {0.f, 0.f, 0.f, 0.f};
        float ocb[4] = {0.f, 0.f, 0.f, 0.f};
        const int dloc = wid * 8 + r4;
        const int vidx = dloc * 4 + l3;             // kgrp2=0 slot; +256 for kgrp2=1
        const int arown = tid >> 4;
        const float invr = sinv[arown];
        float* arow = attng ? attng + ((size_t)bh * SDIM + qbase + arown) * SDIM : (float*)0;

        #pragma unroll 1
        for (int c = 0; c < n; ++c) {
            const uint4* vc = vimg + (size_t)c * 512;
            uint4 vv0 = vc[vidx];          // kg0, kg1
            uint4 vv1 = vc[vidx + 256];    // kg2, kg3

            const int cb2 = c * 32;
            #define PVS(OC, BX, BY, KG) { \
                uint32_t a[4]; \
                a[0] = scw[r4 * SCW       + cb2 + (KG) * 8 + l3]; \
                a[1] = scw[(r4 + 8) * SCW + cb2 + (KG) * 8 + l3]; \
                a[2] = scw[r4 * SCW       + cb2 + (KG) * 8 + 4 + l3]; \
                a[3] = scw[(r4 + 8) * SCW + cb2 + (KG) * 8 + 4 + l3]; \
                uint32_t b2[2] = {BX, BY}; \
                mma16816h(OC, a, b2); }
            PVS(oca, vv0.x, vv0.y, 0)
            PVS(ocb, vv0.z, vv0.w, 1)
            PVS(oca, vv1.x, vv1.y, 2)
            PVS(ocb, vv1.z, vv1.w, 3)
            #undef PVS

            if (arow) {
                const int jc = c * 64 + (tid & 15) * 4;
                uint2 pk = *(const uint2*)(sc + arown * SCH + jc);
                float2 fa = __half22float2(*(__half2*)&pk.x);
                float2 fb = __half22float2(*(__half2*)&pk.y);
                __stcs((float4*)(arow + jc),
                       make_float4(fa.x * invr, fa.y * invr, fb.x * invr, fb.y * invr));
            }
        }

        // attn tail zeros
        if (arow) {
            for (int j = cendC + (tid & 15) * 4; j < SDIM; j += 64)
                __stcs((float4*)(arow + j), make_float4(0.f, 0.f, 0.f, 0.f));
        }

        // output write (warp-owned 16x8 block)
        {
            const float sv0 = sinv[r4], sv1 = sinv[r4 + 8];
            float* orow = outg + headoff + (size_t)(qbase + r4) * DDIM;
            const int dc = wid * 8 + c0;
            *(float2*)(orow + dc) =
                make_float2((oca[0] + ocb[0]) * sv0, (oca[1] + ocb[1]) * sv0);
            *(float2*)(orow + 8 * DDIM + dc) =
                make_float2((oca[2] + ocb[2]) * sv1, (oca[3] + ocb[3]) * sv1);
        }
        __syncthreads();   // sc/qs reuse guard before next tile
    }
}

extern "C" void kernel_launch(void* const* d_in, const int* in_sizes, int n_in,
                              void* d_out, int out_size) {
    const float* q = (const float*)d_in[0];
    const float* k = (const float*)d_in[1];
    const float* v = (const float*)d_in[2];

    float* out = (float*)d_out;
    const long long OUT_E  = 64LL * 2048 * 64;
    const long long ATTN_E = 64LL * 2048 * 2048;
    float* attn = ((long long)out_size >= OUT_E + ATTN_E) ? out + OUT_E : nullptr;

    {
        dim3 g(32, 64);
        conv_kernel<<<g, 256>>>(k, v);
    }

    cudaFuncSetAttribute(attn_kernel,
                         cudaFuncAttributeMaxDynamicSharedMemorySize, SMEM_BYTES);
    dim3 grid(64, 64);   // 64 balanced tile-pairs x 64 heads
    attn_kernel<<<grid, NTHREADS, SMEM_BYTES>>>(q, out, attn);
}